// round 4
// baseline (speedup 1.0000x reference)
#include <cuda_runtime.h>
#include <cuda_fp16.h>

#define DIM 128
#define HEADS 4
#define NMAX 50000
#define BCAP 64
#define OVF_CAP 2048

// ---- device scratch ----
__device__ __half d_h16[NMAX * DIM];
__device__ __half d_x16[NMAX * DIM];
__device__ float d_asrc[NMAX * HEADS];
__device__ float d_adst[NMAX * HEADS];
__device__ float d_B[DIM * DIM];
__device__ float d_C[DIM * DIM];
__device__ float d_dvec[DIM];
__device__ int   d_fill[NMAX];
__device__ int   d_esrc[NMAX * BCAP];
__device__ int   d_ovf[OVF_CAP * 2];
__device__ int   d_ovf_cnt;
__device__ int   d_is64;

__device__ __forceinline__ void mma_tf32(float c[4], unsigned a0, unsigned a1,
                                         unsigned a2, unsigned a3,
                                         unsigned b0, unsigned b1) {
    asm volatile(
        "mma.sync.aligned.m16n8k8.row.col.f32.tf32.tf32.f32 "
        "{%0,%1,%2,%3}, {%4,%5,%6,%7}, {%8,%9}, {%0,%1,%2,%3};"
        : "+f"(c[0]), "+f"(c[1]), "+f"(c[2]), "+f"(c[3])
        : "r"(a0), "r"(a1), "r"(a2), "r"(a3), "r"(b0), "r"(b1));
}

__device__ __forceinline__ void cp16(void* sptr, const void* g, int srcsize) {
    unsigned sm = (unsigned)__cvta_generic_to_shared(sptr);
    asm volatile("cp.async.cg.shared.global [%0], [%1], 16, %2;"
                 :: "r"(sm), "l"(g), "r"(srcsize));
}
#define CP_COMMIT() asm volatile("cp.async.commit_group;")
#define CP_WAIT(N)  asm volatile("cp.async.wait_group %0;" :: "n"(N))

// mma over full K=128 segment: A [64][132] raw-fp32-as-tf32, W [128][136]
__device__ __forceinline__ void mma_seg(const float* A, const float* W, float c[8][4],
                                        int warpM, int warpN, int g, int tig) {
#pragma unroll
    for (int k8 = 0; k8 < 128; k8 += 8) {
        unsigned a0 = __float_as_uint(A[(warpM * 16 + g) * 132 + k8 + tig]);
        unsigned a1 = __float_as_uint(A[(warpM * 16 + g + 8) * 132 + k8 + tig]);
        unsigned a2 = __float_as_uint(A[(warpM * 16 + g) * 132 + k8 + tig + 4]);
        unsigned a3 = __float_as_uint(A[(warpM * 16 + g + 8) * 132 + k8 + tig + 4]);
#pragma unroll
        for (int n8 = 0; n8 < 8; n8++) {
            int cb = warpN * 64 + n8 * 8 + g;
            unsigned b0 = __float_as_uint(W[(k8 + tig) * 136 + cb]);
            unsigned b1 = __float_as_uint(W[(k8 + tig + 4) * 136 + cb]);
            mma_tf32(c[n8], a0, a1, a2, a3, b0, b1);
        }
    }
}

// ---- init: zero fill counters + detect int64 ----
__global__ void k_init(const unsigned* __restrict__ e, int n) {
    int t = blockIdx.x * blockDim.x + threadIdx.x;
    if (t < n) d_fill[t] = 0;
    if (t == 0) {
        d_ovf_cnt = 0;
        int all0 = 1;
        for (int i = 1; i < 64; i += 2) all0 &= (e[i] == 0u);
        d_is64 = all0;
    }
}

// ---- precompose: B = Wl@Wp2, C = Wr@Wp2 + I, dvec = bl@Wp2 + bp ----
__global__ void k_prep(const float* __restrict__ Wl, const float* __restrict__ Wr,
                       const float* __restrict__ bl, const float* __restrict__ Wp,
                       const float* __restrict__ bp) {
    const float* Wp2 = Wp + DIM * DIM;
    if (blockIdx.x == 4) {
        int nn = threadIdx.x;
        if (nn < DIM) {
            float s = bp[nn];
            for (int j = 0; j < DIM; j++) s += bl[j] * Wp2[j * DIM + nn];
            d_dvec[nn] = s;
        }
        return;
    }
    __shared__ float xs[64][16];
    __shared__ float ws[16][128];
    int tid = threadIdx.x, tx = tid & 31, ty = tid >> 5;
    int rowBase = blockIdx.x * 64;
    const float* A = (rowBase < 128) ? Wl : Wr;
    int aBase = (rowBase < 128) ? rowBase : rowBase - 128;
    float acc[8][4];
#pragma unroll
    for (int r = 0; r < 8; r++) { acc[r][0] = acc[r][1] = acc[r][2] = acc[r][3] = 0.f; }
    for (int kk = 0; kk < 8; kk++) {
        int r = tid >> 2, k4 = (tid & 3) << 2;
        *(float4*)&xs[r][k4] = *(const float4*)&A[(size_t)(aBase + r) * DIM + kk * 16 + k4];
#pragma unroll
        for (int i = 0; i < 2; i++) {
            int id = tid + i * 256;
            int wr = id >> 5, wc = (id & 31) << 2;
            *(float4*)&ws[wr][wc] = *(const float4*)&Wp2[(size_t)(kk * 16 + wr) * DIM + wc];
        }
        __syncthreads();
#pragma unroll
        for (int k = 0; k < 16; k++) {
            float4 b = *(float4*)&ws[k][tx << 2];
#pragma unroll
            for (int r8 = 0; r8 < 8; r8++) {
                float a = xs[ty * 8 + r8][k];
                acc[r8][0] += a * b.x; acc[r8][1] += a * b.y;
                acc[r8][2] += a * b.z; acc[r8][3] += a * b.w;
            }
        }
        __syncthreads();
    }
#pragma unroll
    for (int r8 = 0; r8 < 8; r8++) {
        int vr = rowBase + ty * 8 + r8;
        int col = tx << 2;
        if (vr < 128) {
            *(float4*)&d_B[vr * DIM + col] =
                make_float4(acc[r8][0], acc[r8][1], acc[r8][2], acc[r8][3]);
        } else {
            int rr = vr - 128;
            float4 v = make_float4(acc[r8][0], acc[r8][1], acc[r8][2], acc[r8][3]);
            if (rr >= col && rr < col + 4) {
                if (rr == col) v.x += 1.f;
                else if (rr == col + 1) v.y += 1.f;
                else if (rr == col + 2) v.z += 1.f;
                else v.w += 1.f;
            }
            *(float4*)&d_C[rr * DIM + col] = v;
        }
    }
}

// ---- scatter: 4 edges per thread (MLP) ----
__global__ void k_scatter(const int* __restrict__ eidx, int E) {
    int is64 = d_is64;
    int t = blockIdx.x * blockDim.x + threadIdx.x;
    int base = t * 4;
    if (base >= E) return;
    int m = E - base; if (m > 4) m = 4;
    int s[4], d[4];
    if (is64) {
        const long long* p = (const long long*)eidx;
#pragma unroll
        for (int j = 0; j < 4; j++) if (j < m) {
            s[j] = (int)__ldg(&p[base + j]); d[j] = (int)__ldg(&p[E + base + j]);
        }
    } else {
#pragma unroll
        for (int j = 0; j < 4; j++) if (j < m) {
            s[j] = __ldg(&eidx[base + j]); d[j] = __ldg(&eidx[E + base + j]);
        }
    }
#pragma unroll
    for (int j = 0; j < 4; j++) if (j < m) {
        int slot = atomicAdd(&d_fill[d[j]], 1);
        if (slot < BCAP) {
            d_esrc[d[j] * BCAP + slot] = s[j];
        } else {
            int o = atomicAdd(&d_ovf_cnt, 1);
            if (o < OVF_CAP) { d_ovf[2 * o] = s[j]; d_ovf[2 * o + 1] = d[j]; }
        }
    }
}

// ---- GEMM1 (tf32, full-K staged, cp.async): h = x @ W_gat
//      + fused attn logits + h16 store + x16 store ----
__global__ void k_gemm_h(const float* __restrict__ x, const float* __restrict__ W,
                         const float* __restrict__ att_src, const float* __restrict__ att_dst,
                         int n) {
    extern __shared__ float sm[];
    float* xs = sm;              // [64][132] raw x / later frag dump
    float* ws = sm + 64 * 132;   // [128][136]
    int tid = threadIdx.x, lane = tid & 31, wid = tid >> 5;
    int rowBase = blockIdx.x * 64;
    int warpM = wid & 3, warpN = wid >> 2;
    int g = lane >> 2, tig = lane & 3;

    // stage A (x tile) + W fully
#pragma unroll
    for (int i = 0; i < 8; i++) {
        int chunk = tid + i * 256;
        int r = chunk >> 5, c4 = (chunk & 31) << 2;
        int gr = rowBase + r;
        cp16(&xs[r * 132 + c4], &x[(size_t)gr * DIM + c4], gr < n ? 16 : 0);
    }
#pragma unroll
    for (int i = 0; i < 16; i++) {
        int chunk = tid + i * 256;
        int wr = chunk >> 5, wc = (chunk & 31) << 2;
        cp16(&ws[wr * 136 + wc], &W[(size_t)wr * DIM + wc], 16);
    }
    CP_COMMIT();
    CP_WAIT(0);
    __syncthreads();

    float c[8][4];
#pragma unroll
    for (int i = 0; i < 8; i++) { c[i][0] = c[i][1] = c[i][2] = c[i][3] = 0.f; }
    mma_seg(xs, ws, c, warpM, warpN, g, tig);

    // x16 store from raw xs (before overwrite)
    int tx = lane, ty = wid;
#pragma unroll
    for (int r8 = 0; r8 < 8; r8++) {
        int gr = rowBase + ty * 8 + r8;
        if (gr < n) {
            float4 v = *(float4*)&xs[(ty * 8 + r8) * 132 + (tx << 2)];
            __half2 p0 = __floats2half2_rn(v.x, v.y);
            __half2 p1 = __floats2half2_rn(v.z, v.w);
            uint2 q; q.x = *(unsigned*)&p0; q.y = *(unsigned*)&p1;
            *(uint2*)&d_x16[(size_t)gr * DIM + (tx << 2)] = q;
        }
    }
    __syncthreads();
    // dump frags into xs
    {
        int rb = warpM * 16, cb = warpN * 64;
#pragma unroll
        for (int n8 = 0; n8 < 8; n8++) {
            int cc = cb + n8 * 8 + 2 * tig;
            xs[(rb + g) * 132 + cc] = c[n8][0];     xs[(rb + g) * 132 + cc + 1] = c[n8][1];
            xs[(rb + g + 8) * 132 + cc] = c[n8][2]; xs[(rb + g + 8) * 132 + cc + 1] = c[n8][3];
        }
    }
    __syncthreads();
    // h16 store + attn logits
    float4 as4 = *(const float4*)&att_src[tx << 2];
    float4 ad4 = *(const float4*)&att_dst[tx << 2];
#pragma unroll
    for (int r8 = 0; r8 < 8; r8++) {
        int gr = rowBase + ty * 8 + r8;
        float4 hv = *(float4*)&xs[(ty * 8 + r8) * 132 + (tx << 2)];
        if (gr < n) {
            __half2 p0 = __floats2half2_rn(hv.x, hv.y);
            __half2 p1 = __floats2half2_rn(hv.z, hv.w);
            uint2 q; q.x = *(unsigned*)&p0; q.y = *(unsigned*)&p1;
            *(uint2*)&d_h16[(size_t)gr * DIM + (tx << 2)] = q;
        }
        float ps = hv.x * as4.x + hv.y * as4.y + hv.z * as4.z + hv.w * as4.w;
        float pd = hv.x * ad4.x + hv.y * ad4.y + hv.z * ad4.z + hv.w * ad4.w;
#pragma unroll
        for (int o = 4; o; o >>= 1) {
            ps += __shfl_xor_sync(0xffffffffu, ps, o);
            pd += __shfl_xor_sync(0xffffffffu, pd, o);
        }
        if ((tx & 7) == 0 && gr < n) {
            int hd = tx >> 3;
            d_asrc[gr * 4 + hd] = ps;
            d_adst[gr * 4 + hd] = pd;
        }
    }
}

// ---- fused gather + 3-seg GEMM + LayerNorm ----
__global__ void k_fuse(const float* __restrict__ x, const float* __restrict__ Wp,
                       const float* __restrict__ b_gat,
                       const float* __restrict__ gamma, const float* __restrict__ beta,
                       float* __restrict__ out, int n) {
    extern __shared__ float sm[];
    float* ga = sm;                       // [64][132] gat_out -> later x tile
    float* sa = sm + 8448;                // [64][132] sage mean -> later frag dump
    float* w0 = sm + 16896;               // [128][136]
    float* w1 = sm + 16896 + 17408;       // [128][136]
    int tid = threadIdx.x, lane = tid & 31, wid = tid >> 5;
    int rowBase = blockIdx.x * 64;
    int warpM = wid & 3, warpN = wid >> 2;
    int g = lane >> 2, tig = lane & 3;

    // prefetch seg0 weights (Wp rows 0..127) during gather
#pragma unroll
    for (int i = 0; i < 16; i++) {
        int chunk = tid + i * 256;
        int wr = chunk >> 5, wc = (chunk & 31) << 2;
        cp16(&w0[wr * 136 + wc], &Wp[(size_t)wr * DIM + wc], 16);
    }
    CP_COMMIT();  // group 1

    // ---- gather phase: each warp handles 8 nodes ----
    int hd = lane >> 3;
    int cc4 = lane << 2;
    int oc = d_ovf_cnt; if (oc > OVF_CAP) oc = OVF_CAP;
    for (int i8 = 0; i8 < 8; i8++) {
        int nd = rowBase + wid * 8 + i8;
        float* gaRow = &ga[(wid * 8 + i8) * 132 + cc4];
        float* saRow = &sa[(wid * 8 + i8) * 132 + cc4];
        if (nd >= n) {
            *(float4*)gaRow = make_float4(0.f, 0.f, 0.f, 0.f);
            *(float4*)saRow = make_float4(0.f, 0.f, 0.f, 0.f);
            continue;
        }
        int fill = d_fill[nd];
        int deg = fill < BCAP ? fill : BCAP;
        float adst = d_adst[nd * 4 + hd];
        float4 gv = make_float4(0.f, 0.f, 0.f, 0.f);
        float4 sv = make_float4(0.f, 0.f, 0.f, 0.f);
        float den = 0.f;
        for (int base = 0; base < deg; base += 32) {
            int cnt = deg - base; if (cnt > 32) cnt = 32;
            int myS = (lane < cnt) ? d_esrc[nd * BCAP + base + lane] : 0;
#pragma unroll 8
            for (int j = 0; j < cnt; j++) {
                int s = __shfl_sync(0xffffffffu, myS, j);
                float asr = __ldg(&d_asrc[s * 4 + hd]);
                float ee = asr + adst;
                ee = ee > 0.f ? ee : 0.2f * ee;
                float ex = __expf(ee);
                den += ex;
                uint2 hraw = __ldg((const uint2*)&d_h16[(size_t)s * DIM + cc4]);
                uint2 xraw = __ldg((const uint2*)&d_x16[(size_t)s * DIM + cc4]);
                float2 h01 = __half22float2(*(__half2*)&hraw.x);
                float2 h23 = __half22float2(*(__half2*)&hraw.y);
                float2 x01 = __half22float2(*(__half2*)&xraw.x);
                float2 x23 = __half22float2(*(__half2*)&xraw.y);
                gv.x += h01.x * ex; gv.y += h01.y * ex; gv.z += h23.x * ex; gv.w += h23.y * ex;
                sv.x += x01.x; sv.y += x01.y; sv.z += x23.x; sv.w += x23.y;
            }
        }
        // overflow edges (normally zero)
        for (int k = 0; k < oc; k++) {
            if (d_ovf[2 * k + 1] == nd) {
                int s = d_ovf[2 * k];
                float asr = __ldg(&d_asrc[s * 4 + hd]);
                float ee = asr + adst;
                ee = ee > 0.f ? ee : 0.2f * ee;
                float ex = __expf(ee);
                den += ex;
                uint2 hraw = __ldg((const uint2*)&d_h16[(size_t)s * DIM + cc4]);
                uint2 xraw = __ldg((const uint2*)&d_x16[(size_t)s * DIM + cc4]);
                float2 h01 = __half22float2(*(__half2*)&hraw.x);
                float2 h23 = __half22float2(*(__half2*)&hraw.y);
                float2 x01 = __half22float2(*(__half2*)&xraw.x);
                float2 x23 = __half22float2(*(__half2*)&xraw.y);
                gv.x += h01.x * ex; gv.y += h01.y * ex; gv.z += h23.x * ex; gv.w += h23.y * ex;
                sv.x += x01.x; sv.y += x01.y; sv.z += x23.x; sv.w += x23.y;
            }
        }
        // self-loop (GAT only)
        {
            float asr = d_asrc[nd * 4 + hd];
            float ee = asr + adst;
            ee = ee > 0.f ? ee : 0.2f * ee;
            float exs = __expf(ee);
            den += exs;
            uint2 hraw = __ldg((const uint2*)&d_h16[(size_t)nd * DIM + cc4]);
            float2 h01 = __half22float2(*(__half2*)&hraw.x);
            float2 h23 = __half22float2(*(__half2*)&hraw.y);
            gv.x += h01.x * exs; gv.y += h01.y * exs; gv.z += h23.x * exs; gv.w += h23.y * exs;
        }
        float inv = 1.f / (den + 1e-16f);
        float4 bg = *(const float4*)&b_gat[cc4];
        *(float4*)gaRow = make_float4(gv.x * inv + bg.x, gv.y * inv + bg.y,
                                      gv.z * inv + bg.z, gv.w * inv + bg.w);
        float dg = fill > 0 ? (float)fill : 1.f;
        float idg = 1.f / dg;
        *(float4*)saRow = make_float4(sv.x * idg, sv.y * idg, sv.z * idg, sv.w * idg);
    }
    __syncthreads();

    // stage seg1 weights (d_B)
#pragma unroll
    for (int i = 0; i < 16; i++) {
        int chunk = tid + i * 256;
        int wr = chunk >> 5, wc = (chunk & 31) << 2;
        cp16(&w1[wr * 136 + wc], &d_B[wr * DIM + wc], 16);
    }
    CP_COMMIT();  // group 2
    CP_WAIT(1);   // group 1 (w0) done
    __syncthreads();

    float c[8][4];
#pragma unroll
    for (int i = 0; i < 8; i++) { c[i][0] = c[i][1] = c[i][2] = c[i][3] = 0.f; }

    // seg0: gat @ Wp1
    mma_seg(ga, w0, c, warpM, warpN, g, tig);
    __syncthreads();  // done reading ga, w0

    // stage x tile -> ga, seg2 weights (d_C) -> w0
#pragma unroll
    for (int i = 0; i < 8; i++) {
        int chunk = tid + i * 256;
        int r = chunk >> 5, c4 = (chunk & 31) << 2;
        int gr = rowBase + r;
        cp16(&ga[r * 132 + c4], &x[(size_t)gr * DIM + c4], gr < n ? 16 : 0);
    }
#pragma unroll
    for (int i = 0; i < 16; i++) {
        int chunk = tid + i * 256;
        int wr = chunk >> 5, wc = (chunk & 31) << 2;
        cp16(&w0[wr * 136 + wc], &d_C[wr * DIM + wc], 16);
    }
    CP_COMMIT();  // group 3
    CP_WAIT(1);   // group 2 (w1) done
    __syncthreads();

    // seg1: sage @ B
    mma_seg(sa, w1, c, warpM, warpN, g, tig);
    __syncthreads();
    CP_WAIT(0);   // group 3 (x, w0=C) done
    __syncthreads();

    // seg2: x @ C
    mma_seg(ga, w0, c, warpM, warpN, g, tig);
    __syncthreads();

    // dump frags -> sa
    {
        int rb = warpM * 16, cb = warpN * 64;
#pragma unroll
        for (int n8 = 0; n8 < 8; n8++) {
            int cq = cb + n8 * 8 + 2 * tig;
            sa[(rb + g) * 132 + cq] = c[n8][0];     sa[(rb + g) * 132 + cq + 1] = c[n8][1];
            sa[(rb + g + 8) * 132 + cq] = c[n8][2]; sa[(rb + g + 8) * 132 + cq + 1] = c[n8][3];
        }
    }
    __syncthreads();

    // LayerNorm epilogue
    int tx = lane, ty = wid;
    float4 dv = *(const float4*)&d_dvec[tx << 2];
    float4 gm = *(const float4*)&gamma[tx << 2];
    float4 bt = *(const float4*)&beta[tx << 2];
#pragma unroll
    for (int r8 = 0; r8 < 8; r8++) {
        float4 av = *(float4*)&sa[(ty * 8 + r8) * 132 + (tx << 2)];
        float v0 = av.x + dv.x, v1 = av.y + dv.y;
        float v2 = av.z + dv.z, v3 = av.w + dv.w;
        float sum = v0 + v1 + v2 + v3;
        float sq = v0 * v0 + v1 * v1 + v2 * v2 + v3 * v3;
#pragma unroll
        for (int o = 16; o; o >>= 1) {
            sum += __shfl_xor_sync(0xffffffffu, sum, o);
            sq  += __shfl_xor_sync(0xffffffffu, sq, o);
        }
        float mu = sum * (1.f / 128.f);
        float var = sq * (1.f / 128.f) - mu * mu;
        float rstd = rsqrtf(var + 1e-5f);
        int gr = rowBase + ty * 8 + r8;
        if (gr < n) {
            float4 o4;
            o4.x = (v0 - mu) * rstd * gm.x + bt.x;
            o4.y = (v1 - mu) * rstd * gm.y + bt.y;
            o4.z = (v2 - mu) * rstd * gm.z + bt.z;
            o4.w = (v3 - mu) * rstd * gm.w + bt.w;
            *(float4*)&out[(size_t)gr * DIM + (tx << 2)] = o4;
        }
    }
}

extern "C" void kernel_launch(void* const* d_in, const int* in_sizes, int n_in,
                              void* d_out, int out_size) {
    const float* x       = (const float*)d_in[0];
    const void*  eidx    = d_in[1];
    const float* W_gat   = (const float*)d_in[2];
    const float* att_src = (const float*)d_in[3];
    const float* att_dst = (const float*)d_in[4];
    const float* b_gat   = (const float*)d_in[5];
    const float* W_l     = (const float*)d_in[6];
    const float* b_l     = (const float*)d_in[7];
    const float* W_r     = (const float*)d_in[8];
    const float* W_proj  = (const float*)d_in[9];
    const float* b_proj  = (const float*)d_in[10];
    const float* gamma   = (const float*)d_in[11];
    const float* beta    = (const float*)d_in[12];

    int n = in_sizes[0] / DIM;
    int E = in_sizes[1] / 2;

    const int SMEM_GH = (64 * 132 + 128 * 136) * 4;          // 103,424 B
    const int SMEM_FU = (2 * 64 * 132 + 2 * 128 * 136) * 4;  // 206,848 B
    cudaFuncSetAttribute(k_gemm_h, cudaFuncAttributeMaxDynamicSharedMemorySize, SMEM_GH);
    cudaFuncSetAttribute(k_fuse,   cudaFuncAttributeMaxDynamicSharedMemorySize, SMEM_FU);

    k_init<<<(n + 255) / 256, 256>>>((const unsigned*)eidx, n);                 // 1
    k_prep<<<5, 256>>>(W_l, W_r, b_l, W_proj, b_proj);                          // 2
    k_scatter<<<((E + 3) / 4 + 255) / 256, 256>>>((const int*)eidx, E);         // 3
    k_gemm_h<<<(n + 63) / 64, 256, SMEM_GH>>>(x, W_gat, att_src, att_dst, n);   // 4
    k_fuse<<<(n + 63) / 64, 256, SMEM_FU>>>(x, W_proj, b_gat, gamma, beta,
                                            (float*)d_out, n);                  // 5
}

// round 5
// speedup vs baseline: 1.6749x; 1.6749x over previous
#include <cuda_runtime.h>
#include <cuda_fp16.h>

#define DIM 128
#define HEADS 4
#define NMAX 50000
#define BCAP 64
#define OVF_CAP 2048

// ---- device scratch ----
__device__ __half d_hx16[NMAX * 256];    // interleaved per node: [h(4c..4c+3), x(4c..4c+3)] per lane c
__device__ float d_asrc[NMAX * HEADS];
__device__ float d_adst[NMAX * HEADS];
__device__ float d_gacc[NMAX * DIM];
__device__ float d_sacc[NMAX * DIM];
__device__ float d_B[DIM * DIM];
__device__ float d_C[DIM * DIM];
__device__ float d_dvec[DIM];
__device__ int   d_fill[NMAX];
__device__ int   d_esrc[NMAX * BCAP];
__device__ int   d_ovf[OVF_CAP * 2];
__device__ int   d_ovf_cnt;
__device__ int   d_is64;

__device__ __forceinline__ void mma_tf32(float c[4], unsigned a0, unsigned a1,
                                         unsigned a2, unsigned a3,
                                         unsigned b0, unsigned b1) {
    asm volatile(
        "mma.sync.aligned.m16n8k8.row.col.f32.tf32.tf32.f32 "
        "{%0,%1,%2,%3}, {%4,%5,%6,%7}, {%8,%9}, {%0,%1,%2,%3};"
        : "+f"(c[0]), "+f"(c[1]), "+f"(c[2]), "+f"(c[3])
        : "r"(a0), "r"(a1), "r"(a2), "r"(a3), "r"(b0), "r"(b1));
}

__device__ __forceinline__ void cp16(void* sptr, const void* g, int srcsize) {
    unsigned sm = (unsigned)__cvta_generic_to_shared(sptr);
    asm volatile("cp.async.cg.shared.global [%0], [%1], 16, %2;"
                 :: "r"(sm), "l"(g), "r"(srcsize));
}
#define CP_COMMIT() asm volatile("cp.async.commit_group;")
#define CP_WAIT0()  asm volatile("cp.async.wait_group 0;")

// mma over full K=128 segment: A [64][132] raw fp32 bits, W [128][136]
__device__ __forceinline__ void mma_seg(const float* A, const float* W, float c[8][4],
                                        int warpM, int warpN, int g, int tig) {
#pragma unroll
    for (int k8 = 0; k8 < 128; k8 += 8) {
        unsigned a0 = __float_as_uint(A[(warpM * 16 + g) * 132 + k8 + tig]);
        unsigned a1 = __float_as_uint(A[(warpM * 16 + g + 8) * 132 + k8 + tig]);
        unsigned a2 = __float_as_uint(A[(warpM * 16 + g) * 132 + k8 + tig + 4]);
        unsigned a3 = __float_as_uint(A[(warpM * 16 + g + 8) * 132 + k8 + tig + 4]);
#pragma unroll
        for (int n8 = 0; n8 < 8; n8++) {
            int cb = warpN * 64 + n8 * 8 + g;
            unsigned b0 = __float_as_uint(W[(k8 + tig) * 136 + cb]);
            unsigned b1 = __float_as_uint(W[(k8 + tig + 4) * 136 + cb]);
            mma_tf32(c[n8], a0, a1, a2, a3, b0, b1);
        }
    }
}

// ---- init: zero fill counters + detect int64 ----
__global__ void k_init(const unsigned* __restrict__ e, int n) {
    int t = blockIdx.x * blockDim.x + threadIdx.x;
    if (t < n) d_fill[t] = 0;
    if (t == 0) {
        d_ovf_cnt = 0;
        int all0 = 1;
        for (int i = 1; i < 64; i += 2) all0 &= (e[i] == 0u);
        d_is64 = all0;
    }
}

// ---- GEMM1 (tf32, full-K, cp.async): h = x @ W_gat + attn logits + interleaved hx store ----
__global__ void k_gemm_h(const float* __restrict__ x, const float* __restrict__ W,
                         const float* __restrict__ att_src, const float* __restrict__ att_dst,
                         int n) {
    extern __shared__ float sm[];
    float* xs = sm;              // [64][132] raw x / later frag dump
    float* ws = sm + 64 * 132;   // [128][136]
    int tid = threadIdx.x, lane = tid & 31, wid = tid >> 5;
    int rowBase = blockIdx.x * 64;
    int warpM = wid & 3, warpN = wid >> 2;
    int g = lane >> 2, tig = lane & 3;

#pragma unroll
    for (int i = 0; i < 8; i++) {
        int chunk = tid + i * 256;
        int r = chunk >> 5, c4 = (chunk & 31) << 2;
        int gr = rowBase + r;
        cp16(&xs[r * 132 + c4], &x[(size_t)gr * DIM + c4], gr < n ? 16 : 0);
    }
#pragma unroll
    for (int i = 0; i < 16; i++) {
        int chunk = tid + i * 256;
        int wr = chunk >> 5, wc = (chunk & 31) << 2;
        cp16(&ws[wr * 136 + wc], &W[(size_t)wr * DIM + wc], 16);
    }
    CP_COMMIT();
    CP_WAIT0();
    __syncthreads();

    float c[8][4];
#pragma unroll
    for (int i = 0; i < 8; i++) { c[i][0] = c[i][1] = c[i][2] = c[i][3] = 0.f; }
    mma_seg(xs, ws, c, warpM, warpN, g, tig);

    // x-part of interleaved hx store (from raw xs, before overwrite)
    int tx = lane, ty = wid;
#pragma unroll
    for (int r8 = 0; r8 < 8; r8++) {
        int gr = rowBase + ty * 8 + r8;
        if (gr < n) {
            float4 v = *(float4*)&xs[(ty * 8 + r8) * 132 + (tx << 2)];
            __half2 p0 = __floats2half2_rn(v.x, v.y);
            __half2 p1 = __floats2half2_rn(v.z, v.w);
            uint2 q; q.x = *(unsigned*)&p0; q.y = *(unsigned*)&p1;
            *(uint2*)&d_hx16[(size_t)gr * 256 + tx * 8 + 4] = q;
        }
    }
    __syncthreads();
    // dump frags into xs
    {
        int rb = warpM * 16, cb = warpN * 64;
#pragma unroll
        for (int n8 = 0; n8 < 8; n8++) {
            int cc = cb + n8 * 8 + 2 * tig;
            xs[(rb + g) * 132 + cc] = c[n8][0];     xs[(rb + g) * 132 + cc + 1] = c[n8][1];
            xs[(rb + g + 8) * 132 + cc] = c[n8][2]; xs[(rb + g + 8) * 132 + cc + 1] = c[n8][3];
        }
    }
    __syncthreads();
    // h-part store + attn logits
    float4 as4 = *(const float4*)&att_src[tx << 2];
    float4 ad4 = *(const float4*)&att_dst[tx << 2];
#pragma unroll
    for (int r8 = 0; r8 < 8; r8++) {
        int gr = rowBase + ty * 8 + r8;
        float4 hv = *(float4*)&xs[(ty * 8 + r8) * 132 + (tx << 2)];
        if (gr < n) {
            __half2 p0 = __floats2half2_rn(hv.x, hv.y);
            __half2 p1 = __floats2half2_rn(hv.z, hv.w);
            uint2 q; q.x = *(unsigned*)&p0; q.y = *(unsigned*)&p1;
            *(uint2*)&d_hx16[(size_t)gr * 256 + tx * 8] = q;
        }
        float ps = hv.x * as4.x + hv.y * as4.y + hv.z * as4.z + hv.w * as4.w;
        float pd = hv.x * ad4.x + hv.y * ad4.y + hv.z * ad4.z + hv.w * ad4.w;
#pragma unroll
        for (int o = 4; o; o >>= 1) {
            ps += __shfl_xor_sync(0xffffffffu, ps, o);
            pd += __shfl_xor_sync(0xffffffffu, pd, o);
        }
        if ((tx & 7) == 0 && gr < n) {
            int hd = tx >> 3;
            d_asrc[gr * 4 + hd] = ps;
            d_adst[gr * 4 + hd] = pd;
        }
    }
}

// ---- scatter: 4 edges per thread ----
__global__ void k_scatter(const int* __restrict__ eidx, int E) {
    int is64 = d_is64;
    int t = blockIdx.x * blockDim.x + threadIdx.x;
    int base = t * 4;
    if (base >= E) return;
    int m = E - base; if (m > 4) m = 4;
    int s[4], d[4];
    if (is64) {
        const long long* p = (const long long*)eidx;
#pragma unroll
        for (int j = 0; j < 4; j++) if (j < m) {
            s[j] = (int)__ldg(&p[base + j]); d[j] = (int)__ldg(&p[E + base + j]);
        }
    } else {
#pragma unroll
        for (int j = 0; j < 4; j++) if (j < m) {
            s[j] = __ldg(&eidx[base + j]); d[j] = __ldg(&eidx[E + base + j]);
        }
    }
#pragma unroll
    for (int j = 0; j < 4; j++) if (j < m) {
        int slot = atomicAdd(&d_fill[d[j]], 1);
        if (slot < BCAP) {
            d_esrc[d[j] * BCAP + slot] = s[j];
        } else {
            int o = atomicAdd(&d_ovf_cnt, 1);
            if (o < OVF_CAP) { d_ovf[2 * o] = s[j]; d_ovf[2 * o + 1] = d[j]; }
        }
    }
}

// ---- gather: warp per dst node, ONE 16B interleaved load per lane per edge ----
__global__ void k_gather(const float* __restrict__ b_gat, int n) {
    int w = (blockIdx.x * blockDim.x + threadIdx.x) >> 5;
    int lane = threadIdx.x & 31;
    if (w >= n) return;
    int hd = lane >> 3;
    int c = lane << 2;
    int fill = d_fill[w];
    int deg = fill < BCAP ? fill : BCAP;
    float adst = d_adst[w * 4 + hd];
    float4 g = make_float4(0.f, 0.f, 0.f, 0.f);
    float4 sa = make_float4(0.f, 0.f, 0.f, 0.f);
    float den = 0.f;
    const uint4* hx = (const uint4*)d_hx16;   // 32 uint4 per node row

    for (int base = 0; base < deg; base += 32) {
        int cnt = deg - base; if (cnt > 32) cnt = 32;
        int myS = (lane < cnt) ? d_esrc[w * BCAP + base + lane] : 0;
#pragma unroll 8
        for (int j = 0; j < cnt; j++) {
            int s = __shfl_sync(0xffffffffu, myS, j);
            float asr = __ldg(&d_asrc[s * 4 + hd]);
            float ee = asr + adst;
            ee = ee > 0.f ? ee : 0.2f * ee;
            float ex = __expf(ee);
            den += ex;
            uint4 q = __ldg(&hx[(size_t)s * 32 + lane]);
            float2 h01 = __half22float2(*(__half2*)&q.x);
            float2 h23 = __half22float2(*(__half2*)&q.y);
            float2 x01 = __half22float2(*(__half2*)&q.z);
            float2 x23 = __half22float2(*(__half2*)&q.w);
            g.x += h01.x * ex; g.y += h01.y * ex; g.z += h23.x * ex; g.w += h23.y * ex;
            sa.x += x01.x; sa.y += x01.y; sa.z += x23.x; sa.w += x23.y;
        }
    }

    int oc = d_ovf_cnt;
    if (oc > 0) {
        if (oc > OVF_CAP) oc = OVF_CAP;
        for (int k = 0; k < oc; k++) {
            if (d_ovf[2 * k + 1] == w) {
                int s = d_ovf[2 * k];
                float asr = __ldg(&d_asrc[s * 4 + hd]);
                float ee = asr + adst;
                ee = ee > 0.f ? ee : 0.2f * ee;
                float ex = __expf(ee);
                den += ex;
                uint4 q = __ldg(&hx[(size_t)s * 32 + lane]);
                float2 h01 = __half22float2(*(__half2*)&q.x);
                float2 h23 = __half22float2(*(__half2*)&q.y);
                float2 x01 = __half22float2(*(__half2*)&q.z);
                float2 x23 = __half22float2(*(__half2*)&q.w);
                g.x += h01.x * ex; g.y += h01.y * ex; g.z += h23.x * ex; g.w += h23.y * ex;
                sa.x += x01.x; sa.y += x01.y; sa.z += x23.x; sa.w += x23.y;
            }
        }
    }

    // self-loop (GAT only)
    {
        float asr = d_asrc[w * 4 + hd];
        float ee = asr + adst;
        ee = ee > 0.f ? ee : 0.2f * ee;
        float exs = __expf(ee);
        den += exs;
        uint4 q = __ldg(&hx[(size_t)w * 32 + lane]);
        float2 h01 = __half22float2(*(__half2*)&q.x);
        float2 h23 = __half22float2(*(__half2*)&q.y);
        g.x += h01.x * exs; g.y += h01.y * exs; g.z += h23.x * exs; g.w += h23.y * exs;
    }

    float inv = 1.f / (den + 1e-16f);
    float4 bg = *(const float4*)&b_gat[c];
    size_t off = (size_t)w * DIM + c;
    *(float4*)&d_gacc[off] = make_float4(g.x * inv + bg.x, g.y * inv + bg.y,
                                         g.z * inv + bg.z, g.w * inv + bg.w);
    float dg = fill > 0 ? (float)fill : 1.f;
    float idg = 1.f / dg;
    *(float4*)&d_sacc[off] = make_float4(sa.x * idg, sa.y * idg, sa.z * idg, sa.w * idg);
}

// ---- precompose: B = Wl@Wp2, C = Wr@Wp2 + I, dvec = bl@Wp2 + bp ----
__global__ void k_prep(const float* __restrict__ Wl, const float* __restrict__ Wr,
                       const float* __restrict__ bl, const float* __restrict__ Wp,
                       const float* __restrict__ bp) {
    const float* Wp2 = Wp + DIM * DIM;
    if (blockIdx.x == 4) {
        int nn = threadIdx.x;
        if (nn < DIM) {
            float s = bp[nn];
            for (int j = 0; j < DIM; j++) s += bl[j] * Wp2[j * DIM + nn];
            d_dvec[nn] = s;
        }
        return;
    }
    __shared__ float xs[64][16];
    __shared__ float ws[16][128];
    int tid = threadIdx.x, tx = tid & 31, ty = tid >> 5;
    int rowBase = blockIdx.x * 64;
    const float* A = (rowBase < 128) ? Wl : Wr;
    int aBase = (rowBase < 128) ? rowBase : rowBase - 128;
    float acc[8][4];
#pragma unroll
    for (int r = 0; r < 8; r++) { acc[r][0] = acc[r][1] = acc[r][2] = acc[r][3] = 0.f; }
    for (int kk = 0; kk < 8; kk++) {
        int r = tid >> 2, k4 = (tid & 3) << 2;
        *(float4*)&xs[r][k4] = *(const float4*)&A[(size_t)(aBase + r) * DIM + kk * 16 + k4];
#pragma unroll
        for (int i = 0; i < 2; i++) {
            int id = tid + i * 256;
            int wr = id >> 5, wc = (id & 31) << 2;
            *(float4*)&ws[wr][wc] = *(const float4*)&Wp2[(size_t)(kk * 16 + wr) * DIM + wc];
        }
        __syncthreads();
#pragma unroll
        for (int k = 0; k < 16; k++) {
            float4 b = *(float4*)&ws[k][tx << 2];
#pragma unroll
            for (int r8 = 0; r8 < 8; r8++) {
                float a = xs[ty * 8 + r8][k];
                acc[r8][0] += a * b.x; acc[r8][1] += a * b.y;
                acc[r8][2] += a * b.z; acc[r8][3] += a * b.w;
            }
        }
        __syncthreads();
    }
#pragma unroll
    for (int r8 = 0; r8 < 8; r8++) {
        int vr = rowBase + ty * 8 + r8;
        int col = tx << 2;
        if (vr < 128) {
            *(float4*)&d_B[vr * DIM + col] =
                make_float4(acc[r8][0], acc[r8][1], acc[r8][2], acc[r8][3]);
        } else {
            int rr = vr - 128;
            float4 v = make_float4(acc[r8][0], acc[r8][1], acc[r8][2], acc[r8][3]);
            if (rr >= col && rr < col + 4) {
                if (rr == col) v.x += 1.f;
                else if (rr == col + 1) v.y += 1.f;
                else if (rr == col + 2) v.z += 1.f;
                else v.w += 1.f;
            }
            *(float4*)&d_C[rr * DIM + col] = v;
        }
    }
}

// ---- final fused 3-GEMM (tf32, K=384, raw-bit operands, cp.async staging) + LN ----
struct SmemGemm { float xs[64][20]; float ws[16][136]; };

__global__ void k_final(const float* __restrict__ x, const float* __restrict__ Wp,
                        const float* __restrict__ gamma, const float* __restrict__ beta,
                        float* __restrict__ out, int n) {
    __shared__ union USm2 { SmemGemm s; float ot[64][132]; } u;
    int tid = threadIdx.x, lane = tid & 31, wid = tid >> 5;
    int rowBase = blockIdx.x * 64;
    int warpM = wid & 3, warpN = wid >> 2;
    int g = lane >> 2, tig = lane & 3;
    float c[8][4];
#pragma unroll
    for (int i = 0; i < 8; i++) { c[i][0] = c[i][1] = c[i][2] = c[i][3] = 0.f; }

    for (int kk = 0; kk < 24; kk++) {
        int seg = kk >> 3;
        int krel = (kk & 7) * 16;
        const float* src = (seg == 0) ? d_gacc : (seg == 1) ? d_sacc : x;
        const float* wseg = (seg == 0) ? Wp : (seg == 1) ? d_B : d_C;
        int r = tid >> 2, k4 = (tid & 3) << 2;
        int gr = rowBase + r;
        cp16(&u.s.xs[r][k4], &src[(size_t)gr * DIM + krel + k4], gr < n ? 16 : 0);
#pragma unroll
        for (int i = 0; i < 2; i++) {
            int id = tid + i * 256;
            int wr = id >> 5, wc = (id & 31) << 2;
            cp16(&u.s.ws[wr][wc], &wseg[(size_t)(krel + wr) * DIM + wc], 16);
        }
        CP_COMMIT();
        CP_WAIT0();
        __syncthreads();
#pragma unroll
        for (int k8 = 0; k8 < 16; k8 += 8) {
            unsigned a0 = __float_as_uint(u.s.xs[warpM * 16 + g][k8 + tig]);
            unsigned a1 = __float_as_uint(u.s.xs[warpM * 16 + g + 8][k8 + tig]);
            unsigned a2 = __float_as_uint(u.s.xs[warpM * 16 + g][k8 + tig + 4]);
            unsigned a3 = __float_as_uint(u.s.xs[warpM * 16 + g + 8][k8 + tig + 4]);
#pragma unroll
            for (int n8 = 0; n8 < 8; n8++) {
                int cb = warpN * 64 + n8 * 8 + g;
                unsigned b0 = __float_as_uint(u.s.ws[k8 + tig][cb]);
                unsigned b1 = __float_as_uint(u.s.ws[k8 + tig + 4][cb]);
                mma_tf32(c[n8], a0, a1, a2, a3, b0, b1);
            }
        }
        __syncthreads();
    }
    {
        int rb = warpM * 16, cb = warpN * 64;
#pragma unroll
        for (int n8 = 0; n8 < 8; n8++) {
            int cc = cb + n8 * 8 + 2 * tig;
            u.ot[rb + g][cc] = c[n8][0];     u.ot[rb + g][cc + 1] = c[n8][1];
            u.ot[rb + g + 8][cc] = c[n8][2]; u.ot[rb + g + 8][cc + 1] = c[n8][3];
        }
    }
    __syncthreads();
    int tx = lane, ty = wid;
    float4 dv = *(const float4*)&d_dvec[tx << 2];
    float4 gm = *(const float4*)&gamma[tx << 2];
    float4 bt = *(const float4*)&beta[tx << 2];
#pragma unroll
    for (int r8 = 0; r8 < 8; r8++) {
        float4 av = *(float4*)&u.ot[ty * 8 + r8][tx << 2];
        float v0 = av.x + dv.x, v1 = av.y + dv.y;
        float v2 = av.z + dv.z, v3 = av.w + dv.w;
        float sum = v0 + v1 + v2 + v3;
        float sq = v0 * v0 + v1 * v1 + v2 * v2 + v3 * v3;
#pragma unroll
        for (int o = 16; o; o >>= 1) {
            sum += __shfl_xor_sync(0xffffffffu, sum, o);
            sq  += __shfl_xor_sync(0xffffffffu, sq, o);
        }
        float mu = sum * (1.f / 128.f);
        float var = sq * (1.f / 128.f) - mu * mu;
        float rstd = rsqrtf(var + 1e-5f);
        int gr = rowBase + ty * 8 + r8;
        if (gr < n) {
            float4 o4;
            o4.x = (v0 - mu) * rstd * gm.x + bt.x;
            o4.y = (v1 - mu) * rstd * gm.y + bt.y;
            o4.z = (v2 - mu) * rstd * gm.z + bt.z;
            o4.w = (v3 - mu) * rstd * gm.w + bt.w;
            *(float4*)&out[(size_t)gr * DIM + (tx << 2)] = o4;
        }
    }
}

extern "C" void kernel_launch(void* const* d_in, const int* in_sizes, int n_in,
                              void* d_out, int out_size) {
    const float* x       = (const float*)d_in[0];
    const void*  eidx    = d_in[1];
    const float* W_gat   = (const float*)d_in[2];
    const float* att_src = (const float*)d_in[3];
    const float* att_dst = (const float*)d_in[4];
    const float* b_gat   = (const float*)d_in[5];
    const float* W_l     = (const float*)d_in[6];
    const float* b_l     = (const float*)d_in[7];
    const float* W_r     = (const float*)d_in[8];
    const float* W_proj  = (const float*)d_in[9];
    const float* b_proj  = (const float*)d_in[10];
    const float* gamma   = (const float*)d_in[11];
    const float* beta    = (const float*)d_in[12];

    int n = in_sizes[0] / DIM;
    int E = in_sizes[1] / 2;

    const int SMEM_GH = (64 * 132 + 128 * 136) * 4;  // 103,424 B
    cudaFuncSetAttribute(k_gemm_h, cudaFuncAttributeMaxDynamicSharedMemorySize, SMEM_GH);

    k_init<<<(n + 255) / 256, 256>>>((const unsigned*)eidx, n);                 // 1
    k_gemm_h<<<(n + 63) / 64, 256, SMEM_GH>>>(x, W_gat, att_src, att_dst, n);   // 2
    k_scatter<<<((E + 3) / 4 + 255) / 256, 256>>>((const int*)eidx, E);         // 3
    k_gather<<<(n * 32 + 255) / 256, 256>>>(b_gat, n);                          // 4 <- ncu capture
    k_prep<<<5, 256>>>(W_l, W_r, b_l, W_proj, b_proj);                          // 5
    k_final<<<(n + 63) / 64, 256>>>(x, W_proj, gamma, beta, (float*)d_out, n);  // 6
}

// round 7
// speedup vs baseline: 1.7633x; 1.0528x over previous
#include <cuda_runtime.h>
#include <cuda_fp16.h>

#define DIM 128
#define HEADS 4
#define NMAX 50000
#define BCAP 64
#define OVF_CAP 2048

// ---- device scratch ----
__device__ __half d_hx16[NMAX * 256];    // interleaved per node: per lane c: [h(4), x(4)] halves
__device__ float d_asrc[NMAX * HEADS];
__device__ float d_adst[NMAX * HEADS];
__device__ float d_gacc[NMAX * DIM];     // gat_out (incl b_gat)
__device__ float d_sacc[NMAX * DIM];     // SAGE mean
__device__ float d_B[DIM * DIM];         // W_sage_l @ Wp2
__device__ float d_C[DIM * DIM];         // W_sage_r @ Wp2 + I
__device__ float d_dvec[DIM];            // b_sage_l @ Wp2 + b_proj
__device__ int   d_fill[NMAX];
__device__ int   d_esrc[NMAX * BCAP];
__device__ int   d_ovf[OVF_CAP * 2];
__device__ int   d_ovf_cnt;
__device__ int   d_is64;

__device__ __forceinline__ void mma_tf32(float c[4], unsigned a0, unsigned a1,
                                         unsigned a2, unsigned a3,
                                         unsigned b0, unsigned b1) {
    asm volatile(
        "mma.sync.aligned.m16n8k8.row.col.f32.tf32.tf32.f32 "
        "{%0,%1,%2,%3}, {%4,%5,%6,%7}, {%8,%9}, {%0,%1,%2,%3};"
        : "+f"(c[0]), "+f"(c[1]), "+f"(c[2]), "+f"(c[3])
        : "r"(a0), "r"(a1), "r"(a2), "r"(a3), "r"(b0), "r"(b1));
}

__device__ __forceinline__ void cp16(void* sptr, const void* g, int srcsize) {
    unsigned sm = (unsigned)__cvta_generic_to_shared(sptr);
    asm volatile("cp.async.cg.shared.global [%0], [%1], 16, %2;"
                 :: "r"(sm), "l"(g), "r"(srcsize));
}
#define CP_COMMIT() asm volatile("cp.async.commit_group;")
#define CP_WAIT_1() asm volatile("cp.async.wait_group 1;")
#define CP_WAIT_0() asm volatile("cp.async.wait_group 0;")

// one k=16 chunk of mma: A [64][20] raw fp32 bits, W [16][136]
__device__ __forceinline__ void mma_chunk(const float* A, const float* W, float c[8][4],
                                          int warpM, int warpN, int g, int tig) {
#pragma unroll
    for (int k8 = 0; k8 < 16; k8 += 8) {
        unsigned a0 = __float_as_uint(A[(warpM * 16 + g) * 20 + k8 + tig]);
        unsigned a1 = __float_as_uint(A[(warpM * 16 + g + 8) * 20 + k8 + tig]);
        unsigned a2 = __float_as_uint(A[(warpM * 16 + g) * 20 + k8 + tig + 4]);
        unsigned a3 = __float_as_uint(A[(warpM * 16 + g + 8) * 20 + k8 + tig + 4]);
#pragma unroll
        for (int n8 = 0; n8 < 8; n8++) {
            int cb = warpN * 64 + n8 * 8 + g;
            unsigned b0 = __float_as_uint(W[(k8 + tig) * 136 + cb]);
            unsigned b1 = __float_as_uint(W[(k8 + tig + 4) * 136 + cb]);
            mma_tf32(c[n8], a0, a1, a2, a3, b0, b1);
        }
    }
}

struct PipeSmem { float a[2][64 * 20]; float w[2][16 * 136]; };

// ---- GEMM1 (chunked, double-buffered): h = x @ W_gat
//      + attn logits + interleaved hx16 stores + housekeeping ----
__global__ void k_gemm_h(const float* __restrict__ x, const float* __restrict__ W,
                         const float* __restrict__ att_src, const float* __restrict__ att_dst,
                         const unsigned* __restrict__ eraw, int n) {
    __shared__ union USm { PipeSmem p; float ot[64 * 132]; } u;
    int tid = threadIdx.x, lane = tid & 31, wid = tid >> 5;
    int rowBase = blockIdx.x * 64;
    int warpM = wid & 3, warpN = wid >> 2;
    int g = lane >> 2, tig = lane & 3;

    // housekeeping: zero fill counters, detect int64
    int zi = rowBase + tid;
    if (tid < 64 && zi < n) d_fill[zi] = 0;
    if (blockIdx.x == 0 && tid == 64) {
        d_ovf_cnt = 0;
        int all0 = 1;
        for (int i = 1; i < 64; i += 2) all0 &= (eraw[i] == 0u);
        d_is64 = all0;
    }

    int r = tid >> 2, c4 = (tid & 3) << 2;
    int gr = rowBase + r;

    cp16(&u.p.a[0][r * 20 + c4], &x[(size_t)gr * DIM + c4], gr < n ? 16 : 0);
#pragma unroll
    for (int i = 0; i < 2; i++) {
        int id = tid + i * 256;
        int wr = id >> 5, wc = (id & 31) << 2;
        cp16(&u.p.w[0][wr * 136 + wc], &W[(size_t)wr * DIM + wc], 16);
    }
    CP_COMMIT();

    float c[8][4];
#pragma unroll
    for (int i = 0; i < 8; i++) { c[i][0] = c[i][1] = c[i][2] = c[i][3] = 0.f; }

    for (int kk = 0; kk < 8; kk++) {
        int b = kk & 1;
        if (kk < 7) {
            int krel = (kk + 1) * 16;
            cp16(&u.p.a[b ^ 1][r * 20 + c4], &x[(size_t)gr * DIM + krel + c4], gr < n ? 16 : 0);
#pragma unroll
            for (int i = 0; i < 2; i++) {
                int id = tid + i * 256;
                int wr = id >> 5, wc = (id & 31) << 2;
                cp16(&u.p.w[b ^ 1][wr * 136 + wc], &W[(size_t)(krel + wr) * DIM + wc], 16);
            }
            CP_COMMIT();
            CP_WAIT_1();
        } else {
            CP_WAIT_0();
        }
        __syncthreads();
        // x-part interleaved hx16 store for this chunk's columns
        if (gr < n) {
            float4 v = *(float4*)&u.p.a[b][r * 20 + c4];
            __half2 p0 = __floats2half2_rn(v.x, v.y);
            __half2 p1 = __floats2half2_rn(v.z, v.w);
            uint2 q; q.x = *(unsigned*)&p0; q.y = *(unsigned*)&p1;
            int laneCol = kk * 4 + (tid & 3);   // column/4
            *(uint2*)&d_hx16[(size_t)gr * 256 + laneCol * 8 + 4] = q;
        }
        mma_chunk(u.p.a[b], u.p.w[b], c, warpM, warpN, g, tig);
        __syncthreads();
    }
    // dump frags -> ot
    {
        int rb = warpM * 16, cb = warpN * 64;
#pragma unroll
        for (int n8 = 0; n8 < 8; n8++) {
            int cc = cb + n8 * 8 + 2 * tig;
            u.ot[(rb + g) * 132 + cc] = c[n8][0];     u.ot[(rb + g) * 132 + cc + 1] = c[n8][1];
            u.ot[(rb + g + 8) * 132 + cc] = c[n8][2]; u.ot[(rb + g + 8) * 132 + cc + 1] = c[n8][3];
        }
    }
    __syncthreads();
    // h-part store + attention logits
    int tx = lane, ty = wid;
    float4 as4 = *(const float4*)&att_src[tx << 2];
    float4 ad4 = *(const float4*)&att_dst[tx << 2];
#pragma unroll
    for (int r8 = 0; r8 < 8; r8++) {
        int grr = rowBase + ty * 8 + r8;
        float4 hv = *(float4*)&u.ot[(ty * 8 + r8) * 132 + (tx << 2)];
        if (grr < n) {
            __half2 p0 = __floats2half2_rn(hv.x, hv.y);
            __half2 p1 = __floats2half2_rn(hv.z, hv.w);
            uint2 q; q.x = *(unsigned*)&p0; q.y = *(unsigned*)&p1;
            *(uint2*)&d_hx16[(size_t)grr * 256 + tx * 8] = q;
        }
        float ps = hv.x * as4.x + hv.y * as4.y + hv.z * as4.z + hv.w * as4.w;
        float pd = hv.x * ad4.x + hv.y * ad4.y + hv.z * ad4.z + hv.w * ad4.w;
#pragma unroll
        for (int o = 4; o; o >>= 1) {
            ps += __shfl_xor_sync(0xffffffffu, ps, o);
            pd += __shfl_xor_sync(0xffffffffu, pd, o);
        }
        if ((tx & 7) == 0 && grr < n) {
            int hd = tx >> 3;
            d_asrc[grr * 4 + hd] = ps;
            d_adst[grr * 4 + hd] = pd;
        }
    }
}

// ---- scatter: 4 edges per thread ----
__global__ void k_scatter(const int* __restrict__ eidx, int E) {
    int is64 = d_is64;
    int t = blockIdx.x * blockDim.x + threadIdx.x;
    int base = t * 4;
    if (base >= E) return;
    int m = E - base; if (m > 4) m = 4;
    int s[4], d[4];
    if (is64) {
        const long long* p = (const long long*)eidx;
#pragma unroll
        for (int j = 0; j < 4; j++) if (j < m) {
            s[j] = (int)__ldg(&p[base + j]); d[j] = (int)__ldg(&p[E + base + j]);
        }
    } else {
#pragma unroll
        for (int j = 0; j < 4; j++) if (j < m) {
            s[j] = __ldg(&eidx[base + j]); d[j] = __ldg(&eidx[E + base + j]);
        }
    }
#pragma unroll
    for (int j = 0; j < 4; j++) if (j < m) {
        int slot = atomicAdd(&d_fill[d[j]], 1);
        if (slot < BCAP) {
            d_esrc[d[j] * BCAP + slot] = s[j];
        } else {
            int o = atomicAdd(&d_ovf_cnt, 1);
            if (o < OVF_CAP) { d_ovf[2 * o] = s[j]; d_ovf[2 * o + 1] = d[j]; }
        }
    }
}

// ---- precompose: B = Wl@Wp2, C = Wr@Wp2 + I, dvec = bl@Wp2 + bp ----
__global__ void k_prep(const float* __restrict__ Wl, const float* __restrict__ Wr,
                       const float* __restrict__ bl, const float* __restrict__ Wp,
                       const float* __restrict__ bp) {
    const float* Wp2 = Wp + DIM * DIM;
    if (blockIdx.x == 4) {
        int nn = threadIdx.x;
        if (nn < DIM) {
            float s = bp[nn];
            for (int j = 0; j < DIM; j++) s += bl[j] * Wp2[j * DIM + nn];
            d_dvec[nn] = s;
        }
        return;
    }
    __shared__ float xs[64][16];
    __shared__ float ws[16][128];
    int tid = threadIdx.x, tx = tid & 31, ty = tid >> 5;
    int rowBase = blockIdx.x * 64;
    const float* A = (rowBase < 128) ? Wl : Wr;
    int aBase = (rowBase < 128) ? rowBase : rowBase - 128;
    float acc[8][4];
#pragma unroll
    for (int rr = 0; rr < 8; rr++) { acc[rr][0] = acc[rr][1] = acc[rr][2] = acc[rr][3] = 0.f; }
    for (int kk = 0; kk < 8; kk++) {
        int r = tid >> 2, k4 = (tid & 3) << 2;
        *(float4*)&xs[r][k4] = *(const float4*)&A[(size_t)(aBase + r) * DIM + kk * 16 + k4];
#pragma unroll
        for (int i = 0; i < 2; i++) {
            int id = tid + i * 256;
            int wr = id >> 5, wc = (id & 31) << 2;
            *(float4*)&ws[wr][wc] = *(const float4*)&Wp2[(size_t)(kk * 16 + wr) * DIM + wc];
        }
        __syncthreads();
#pragma unroll
        for (int k = 0; k < 16; k++) {
            float4 b = *(float4*)&ws[k][tx << 2];
#pragma unroll
            for (int r8 = 0; r8 < 8; r8++) {
                float a = xs[ty * 8 + r8][k];
                acc[r8][0] += a * b.x; acc[r8][1] += a * b.y;
                acc[r8][2] += a * b.z; acc[r8][3] += a * b.w;
            }
        }
        __syncthreads();
    }
#pragma unroll
    for (int r8 = 0; r8 < 8; r8++) {
        int vr = rowBase + ty * 8 + r8;
        int col = tx << 2;
        if (vr < 128) {
            *(float4*)&d_B[vr * DIM + col] =
                make_float4(acc[r8][0], acc[r8][1], acc[r8][2], acc[r8][3]);
        } else {
            int rr = vr - 128;
            float4 v = make_float4(acc[r8][0], acc[r8][1], acc[r8][2], acc[r8][3]);
            if (rr >= col && rr < col + 4) {
                if (rr == col) v.x += 1.f;
                else if (rr == col + 1) v.y += 1.f;
                else if (rr == col + 2) v.z += 1.f;
                else v.w += 1.f;
            }
            *(float4*)&d_C[rr * DIM + col] = v;
        }
    }
}

// ---- gather: warp per dst node; per-lane exp precompute into smem ----
__global__ void k_gather(const float* __restrict__ b_gat, int n) {
    __shared__ float s_ex[8][32][4];
    int wb = threadIdx.x >> 5;
    int w = (blockIdx.x * blockDim.x + threadIdx.x) >> 5;
    int lane = threadIdx.x & 31;
    if (w >= n) return;
    int hd = lane >> 3;
    int c = lane << 2;
    int fill = d_fill[w];
    int deg = fill < BCAP ? fill : BCAP;
    float4 ad4 = *(const float4*)&d_adst[w * 4];
    float4 g = make_float4(0.f, 0.f, 0.f, 0.f);
    float4 sa = make_float4(0.f, 0.f, 0.f, 0.f);
    float den = 0.f;
    const uint4* hx = (const uint4*)d_hx16;

    for (int base = 0; base < deg; base += 32) {
        int cnt = deg - base; if (cnt > 32) cnt = 32;
        int myS = 0;
        float4 ex4 = make_float4(0.f, 0.f, 0.f, 0.f);
        if (lane < cnt) {
            myS = d_esrc[w * BCAP + base + lane];
            float4 as = *(const float4*)&d_asrc[myS * 4];
            float e0 = as.x + ad4.x, e1 = as.y + ad4.y;
            float e2 = as.z + ad4.z, e3 = as.w + ad4.w;
            e0 = e0 > 0.f ? e0 : 0.2f * e0;
            e1 = e1 > 0.f ? e1 : 0.2f * e1;
            e2 = e2 > 0.f ? e2 : 0.2f * e2;
            e3 = e3 > 0.f ? e3 : 0.2f * e3;
            ex4 = make_float4(__expf(e0), __expf(e1), __expf(e2), __expf(e3));
        }
        *(float4*)&s_ex[wb][lane][0] = ex4;
        __syncwarp();
#pragma unroll 8
        for (int j = 0; j < cnt; j++) {
            int s = __shfl_sync(0xffffffffu, myS, j);
            float ex = s_ex[wb][j][hd];
            den += ex;
            uint4 q = __ldg(&hx[(size_t)s * 32 + lane]);
            float2 h01 = __half22float2(*(__half2*)&q.x);
            float2 h23 = __half22float2(*(__half2*)&q.y);
            float2 x01 = __half22float2(*(__half2*)&q.z);
            float2 x23 = __half22float2(*(__half2*)&q.w);
            g.x += h01.x * ex; g.y += h01.y * ex; g.z += h23.x * ex; g.w += h23.y * ex;
            sa.x += x01.x; sa.y += x01.y; sa.z += x23.x; sa.w += x23.y;
        }
        __syncwarp();
    }

    int oc = d_ovf_cnt;
    if (oc > 0) {
        if (oc > OVF_CAP) oc = OVF_CAP;
        for (int k = 0; k < oc; k++) {
            if (d_ovf[2 * k + 1] == w) {
                int s = d_ovf[2 * k];
                float asr = __ldg(&d_asrc[s * 4 + hd]);
                float adst = (hd == 0) ? ad4.x : (hd == 1) ? ad4.y : (hd == 2) ? ad4.z : ad4.w;
                float ee = asr + adst;
                ee = ee > 0.f ? ee : 0.2f * ee;
                float ex = __expf(ee);
                den += ex;
                uint4 q = __ldg(&hx[(size_t)s * 32 + lane]);
                float2 h01 = __half22float2(*(__half2*)&q.x);
                float2 h23 = __half22float2(*(__half2*)&q.y);
                float2 x01 = __half22float2(*(__half2*)&q.z);
                float2 x23 = __half22float2(*(__half2*)&q.w);
                g.x += h01.x * ex; g.y += h01.y * ex; g.z += h23.x * ex; g.w += h23.y * ex;
                sa.x += x01.x; sa.y += x01.y; sa.z += x23.x; sa.w += x23.y;
            }
        }
    }

    // self-loop (GAT only)
    {
        float asr = d_asrc[w * 4 + hd];
        float adst = (hd == 0) ? ad4.x : (hd == 1) ? ad4.y : (hd == 2) ? ad4.z : ad4.w;
        float ee = asr + adst;
        ee = ee > 0.f ? ee : 0.2f * ee;
        float exs = __expf(ee);
        den += exs;
        uint4 q = __ldg(&hx[(size_t)w * 32 + lane]);
        float2 h01 = __half22float2(*(__half2*)&q.x);
        float2 h23 = __half22float2(*(__half2*)&q.y);
        g.x += h01.x * exs; g.y += h01.y * exs; g.z += h23.x * exs; g.w += h23.y * exs;
    }

    float inv = 1.f / (den + 1e-16f);
    float4 bg = *(const float4*)&b_gat[c];
    size_t off = (size_t)w * DIM + c;
    *(float4*)&d_gacc[off] = make_float4(g.x * inv + bg.x, g.y * inv + bg.y,
                                         g.z * inv + bg.z, g.w * inv + bg.w);
    float dg = fill > 0 ? (float)fill : 1.f;
    float idg = 1.f / dg;
    *(float4*)&d_sacc[off] = make_float4(sa.x * idg, sa.y * idg, sa.z * idg, sa.w * idg);
}

// ---- final fused 3-GEMM (K=384, double-buffered cp.async) + LayerNorm ----
__global__ void k_final(const float* __restrict__ x, const float* __restrict__ Wp,
                        const float* __restrict__ gamma, const float* __restrict__ beta,
                        float* __restrict__ out, int n) {
    __shared__ union USm2 { PipeSmem p; float ot[64 * 132]; } u;
    int tid = threadIdx.x, lane = tid & 31, wid = tid >> 5;
    int rowBase = blockIdx.x * 64;
    int warpM = wid & 3, warpN = wid >> 2;
    int g = lane >> 2, tig = lane & 3;
    int r = tid >> 2, c4 = (tid & 3) << 2;
    int gr = rowBase + r;

    float c[8][4];
#pragma unroll
    for (int i = 0; i < 8; i++) { c[i][0] = c[i][1] = c[i][2] = c[i][3] = 0.f; }

    // stage chunk 0 (seg0 = d_gacc, weights Wp rows 0..127)
    cp16(&u.p.a[0][r * 20 + c4], &d_gacc[(size_t)gr * DIM + c4], gr < n ? 16 : 0);
#pragma unroll
    for (int i = 0; i < 2; i++) {
        int id = tid + i * 256;
        int wr = id >> 5, wc = (id & 31) << 2;
        cp16(&u.p.w[0][wr * 136 + wc], &Wp[(size_t)wr * DIM + wc], 16);
    }
    CP_COMMIT();

    for (int kk = 0; kk < 24; kk++) {
        int b = kk & 1;
        if (kk < 23) {
            int k2 = kk + 1;
            int seg = k2 >> 3;
            int krel = (k2 & 7) * 16;
            const float* src = (seg == 0) ? d_gacc : (seg == 1) ? d_sacc : x;
            const float* wseg = (seg == 0) ? Wp : (seg == 1) ? d_B : d_C;
            cp16(&u.p.a[b ^ 1][r * 20 + c4], &src[(size_t)gr * DIM + krel + c4], gr < n ? 16 : 0);
#pragma unroll
            for (int i = 0; i < 2; i++) {
                int id = tid + i * 256;
                int wr = id >> 5, wc = (id & 31) << 2;
                cp16(&u.p.w[b ^ 1][wr * 136 + wc], &wseg[(size_t)(krel + wr) * DIM + wc], 16);
            }
            CP_COMMIT();
            CP_WAIT_1();
        } else {
            CP_WAIT_0();
        }
        __syncthreads();
        mma_chunk(u.p.a[b], u.p.w[b], c, warpM, warpN, g, tig);
        __syncthreads();
    }
    {
        int rb = warpM * 16, cb = warpN * 64;
#pragma unroll
        for (int n8 = 0; n8 < 8; n8++) {
            int cq = cb + n8 * 8 + 2 * tig;
            u.ot[(rb + g) * 132 + cq] = c[n8][0];     u.ot[(rb + g) * 132 + cq + 1] = c[n8][1];
            u.ot[(rb + g + 8) * 132 + cq] = c[n8][2]; u.ot[(rb + g + 8) * 132 + cq + 1] = c[n8][3];
        }
    }
    __syncthreads();
    int tx = lane, ty = wid;
    float4 dv = *(const float4*)&d_dvec[tx << 2];
    float4 gm = *(const float4*)&gamma[tx << 2];
    float4 bt = *(const float4*)&beta[tx << 2];
#pragma unroll
    for (int r8 = 0; r8 < 8; r8++) {
        float4 av = *(float4*)&u.ot[(ty * 8 + r8) * 132 + (tx << 2)];
        float v0 = av.x + dv.x, v1 = av.y + dv.y;
        float v2 = av.z + dv.z, v3 = av.w + dv.w;
        float sum = v0 + v1 + v2 + v3;
        float sq = v0 * v0 + v1 * v1 + v2 * v2 + v3 * v3;
#pragma unroll
        for (int o = 16; o; o >>= 1) {
            sum += __shfl_xor_sync(0xffffffffu, sum, o);
            sq  += __shfl_xor_sync(0xffffffffu, sq, o);
        }
        float mu = sum * (1.f / 128.f);
        float var = sq * (1.f / 128.f) - mu * mu;
        float rstd = rsqrtf(var + 1e-5f);
        int grr = rowBase + ty * 8 + r8;
        if (grr < n) {
            float4 o4;
            o4.x = (v0 - mu) * rstd * gm.x + bt.x;
            o4.y = (v1 - mu) * rstd * gm.y + bt.y;
            o4.z = (v2 - mu) * rstd * gm.z + bt.z;
            o4.w = (v3 - mu) * rstd * gm.w + bt.w;
            *(float4*)&out[(size_t)grr * DIM + (tx << 2)] = o4;
        }
    }
}

extern "C" void kernel_launch(void* const* d_in, const int* in_sizes, int n_in,
                              void* d_out, int out_size) {
    const float* x       = (const float*)d_in[0];
    const void*  eidx    = d_in[1];
    const float* W_gat   = (const float*)d_in[2];
    const float* att_src = (const float*)d_in[3];
    const float* att_dst = (const float*)d_in[4];
    const float* b_gat   = (const float*)d_in[5];
    const float* W_l     = (const float*)d_in[6];
    const float* b_l     = (const float*)d_in[7];
    const float* W_r     = (const float*)d_in[8];
    const float* W_proj  = (const float*)d_in[9];
    const float* b_proj  = (const float*)d_in[10];
    const float* gamma   = (const float*)d_in[11];
    const float* beta    = (const float*)d_in[12];

    int n = in_sizes[0] / DIM;
    int E = in_sizes[1] / 2;
    int nb = (n + 63) / 64;

    k_gemm_h<<<nb, 256>>>(x, W_gat, att_src, att_dst, (const unsigned*)eidx, n);  // 1
    k_scatter<<<((E + 3) / 4 + 255) / 256, 256>>>((const int*)eidx, E);           // 2
    k_prep<<<5, 256>>>(W_l, W_r, b_l, W_proj, b_proj);                            // 3
    k_gather<<<(n * 32 + 255) / 256, 256>>>(b_gat, n);                            // 4 <- ncu capture
    k_final<<<nb, 256>>>(x, W_proj, gamma, beta, (float*)d_out, n);               // 5
}